// round 4
// baseline (speedup 1.0000x reference)
#include <cuda_runtime.h>
#include <cuda_fp16.h>
#include <math.h>

// Problem constants
#define Bn 16
#define Nn 256
#define Fn 64
#define Hn 128

// Table constants
#define Tn 512
#define D_MAX 1.7320509f
#define TROW 256  // bytes per interleaved table row: 16 groups x 16B

// Interleaved table: entry k, feature group g (4 features):
//   bytes [k*256 + g*16 .. +8)  = g[k][4g..4g+3]   (half x4)  "a"
//   bytes [k*256 + g*16+8 .. +16) = g[k+1][4g..4g+3] (half x4) "c"
__device__ uint4 g_table_raw[(Tn * TROW) / 16];

__device__ __forceinline__ float softplus_acc(float x) {
    // matches jax.nn.softplus = logaddexp(x, 0), stable for all x
    return fmaxf(x, 0.0f) + log1pf(expf(-fabsf(x)));
}

__device__ __forceinline__ __half2 u2h2(unsigned v) {
    return *reinterpret_cast<__half2*>(&v);
}

// ---------------------------------------------------------------------------
// Kernel 1: g[k][f] = softplus( sum_h softplus(d_k*w1+b1)*W2[h,f] + b2[f] ),
// written into the interleaved layout: block k writes the "a" slot of entry k
// and the "c" slot of entry k-1.
// ---------------------------------------------------------------------------
__global__ void build_table_kernel(const float* __restrict__ w1,
                                   const float* __restrict__ b1,
                                   const float* __restrict__ W2,
                                   const float* __restrict__ b2) {
    __shared__ float u[Hn];
    const int k = blockIdx.x;
    const int h = threadIdx.x;  // 0..127
    const float d = (float)k * (D_MAX / (float)(Tn - 1));
    u[h] = softplus_acc(fmaf(d, w1[h], b1[h]));
    __syncthreads();
    if (h < Fn) {
        float acc = b2[h];
#pragma unroll
        for (int hh = 0; hh < Hn; ++hh)
            acc = fmaf(u[hh], W2[hh * Fn + h], acc);
        const __half g = __float2half(softplus_acc(acc));
        __half* tabh = (__half*)g_table_raw;
        const int grp = h >> 2, lane = h & 3;
        // "a" slot of entry k
        tabh[k * 128 + grp * 8 + lane] = g;
        // "c" slot of entry k-1
        if (k > 0)
            tabh[(k - 1) * 128 + grp * 8 + 4 + lane] = g;
    }
}

// ---------------------------------------------------------------------------
// Kernel 2: main reduction.
// grid = 128 CTAs (32 output rows each), block = 512 threads (16 warps).
// Thread (fg = tid&15, il = tid>>4) owns features [4fg,4fg+4) of row
// 32*cta + il. Per j: one packed (k,t) word, one float4 f-load (2-way
// broadcast in warp), one LDS.128 with BOTH lerp endpoints.
// ---------------------------------------------------------------------------
__global__ void __launch_bounds__(512, 1)
mp_main_kernel(const float* __restrict__ r, const float* __restrict__ f,
               float* __restrict__ out) {
    extern __shared__ float sm[];
    char* tab = (char*)sm;                    // 512*256B  = 128 KB
    float* fsm = sm + 32768;                  // 256*64 f32 = 64 KB
    unsigned* dsm = (unsigned*)(sm + 49152);  // 32*256 u32 = 32 KB

    const int tid = threadIdx.x;
    const int cta = blockIdx.x;             // 0..127
    const int b = cta >> 3;                 // 8 CTAs per batch element
    const int i0 = (cta & 7) * 32;          // first local row of this tile

    // 1) stage r[b] (256x3 floats) into the f-tile area temporarily
    for (int e = tid; e < Nn * 3; e += 512)
        fsm[e] = r[b * Nn * 3 + e];
    __syncthreads();

    // 2) precompute packed (k, t) for 32 rows x 256 j
    const float scale = (float)(Tn - 1) / D_MAX;
    for (int e = tid; e < 32 * Nn; e += 512) {
        const int il = e >> 8;
        const int j = e & 255;
        const int ig = i0 + il;
        const float dx = fsm[ig * 3 + 0] - fsm[j * 3 + 0];
        const float dy = fsm[ig * 3 + 1] - fsm[j * 3 + 1];
        const float dz = fsm[ig * 3 + 2] - fsm[j * 3 + 2];
        const float s = fmaf(dx, dx, fmaf(dy, dy, dz * dz));
        float d;
        asm("sqrt.approx.f32 %0, %1;" : "=f"(d) : "f"(s));  // sqrt.approx(0)=0
        const float uu = d * scale;
        const int k = min((int)uu, Tn - 2);
        const float t = uu - (float)k;
        const unsigned th = (unsigned)__half_as_ushort(__float2half_rn(t));
        dsm[e] = ((unsigned)k << 16) | th;
    }
    __syncthreads();

    // 3) stage f[b] tile and the interleaved table (overwrites r staging)
    for (int e = tid; e < (Nn * Fn) / 4; e += 512)
        ((float4*)fsm)[e] = ((const float4*)(f + b * Nn * Fn))[e];
    for (int e = tid; e < (Tn * TROW) / 16; e += 512)
        ((uint4*)tab)[e] = g_table_raw[e];
    __syncthreads();

    // 4) main loop over j — 1 row, 4 features per thread
    const int fg = tid & 15;        // feature group
    const int il = tid >> 4;        // local row 0..31
    const unsigned* drow = dsm + il * Nn;
    const float* fjp = fsm + fg * 4;
    const char* tabc = tab + fg * 16;

    float4 acc = make_float4(0.f, 0.f, 0.f, 0.f);

#pragma unroll 4
    for (int j = 0; j < Nn; ++j) {
        const unsigned w = drow[j];
        const float4 fv = *(const float4*)(fjp + j * Fn);

        const unsigned addr = (w >> 16) << 8;  // k * 256
        const uint4 v = *(const uint4*)(tabc + addr);
        const __half2 t2 = u2h2(__byte_perm(w, w, 0x1010));  // (t, t)

        const __half2 A01 = u2h2(v.x), A23 = u2h2(v.y);
        const __half2 C01 = u2h2(v.z), C23 = u2h2(v.w);
        const __half2 G01 = __hfma2(t2, __hsub2(C01, A01), A01);
        const __half2 G23 = __hfma2(t2, __hsub2(C23, A23), A23);
        const float2 g01 = __half22float2(G01);
        const float2 g23 = __half22float2(G23);

        acc.x = fmaf(g01.x, fv.x, acc.x);
        acc.y = fmaf(g01.y, fv.y, acc.y);
        acc.z = fmaf(g23.x, fv.z, acc.z);
        acc.w = fmaf(g23.y, fv.w, acc.w);
    }

    // 5) final softplus + store
    const int row = cta * 32 + il;  // global row index (b*N + i)
    float4 o;
    o.x = softplus_acc(acc.x); o.y = softplus_acc(acc.y);
    o.z = softplus_acc(acc.z); o.w = softplus_acc(acc.w);
    *(float4*)(out + row * Fn + fg * 4) = o;
}

// ---------------------------------------------------------------------------
extern "C" void kernel_launch(void* const* d_in, const int* in_sizes, int n_in,
                              void* d_out, int out_size) {
    const float* r_batch = (const float*)d_in[0];  // [16,256,3]
    const float* f_batch = (const float*)d_in[1];  // [16,256,64]
    const float* w1 = (const float*)d_in[2];       // [128]
    const float* b1 = (const float*)d_in[3];       // [128]
    const float* W2 = (const float*)d_in[4];       // [128,64]
    const float* b2 = (const float*)d_in[5];       // [64]
    float* out = (float*)d_out;                    // [16,256,64]

    build_table_kernel<<<Tn, Hn>>>(w1, b1, W2, b2);

    const int smem_bytes = 128 * 1024 + 64 * 1024 + 32 * 1024;  // 224 KB
    static bool attr_set = false;
    if (!attr_set) {
        cudaFuncSetAttribute(mp_main_kernel,
                             cudaFuncAttributeMaxDynamicSharedMemorySize,
                             smem_bytes);
        attr_set = true;
    }
    mp_main_kernel<<<(Bn * Nn) / 32, 512, smem_bytes>>>(r_batch, f_batch, out);
}

// round 5
// speedup vs baseline: 1.1280x; 1.1280x over previous
#include <cuda_runtime.h>
#include <cuda_fp16.h>
#include <math.h>

// Problem constants
#define Bn 16
#define Nn 256
#define Fn 64
#define Hn 128

// Table constants (nearest-neighbor lookup)
#define Tn 1024
#define D_MAX 1.7320509f
#define TROW 128  // bytes per table row: 64 features x half

// Table row layout (interleaved for conflict-free LDS.128):
//   chunk c (16 bytes), c = 0..7:
//     halves [0..3] = g[k][4c .. 4c+3]
//     halves [4..7] = g[k][32+4c .. 32+4c+3]
__device__ uint4 g_table_raw[(Tn * TROW) / 16];

__device__ __forceinline__ float softplus_acc(float x) {
    // matches jax.nn.softplus = logaddexp(x, 0), stable for all x
    return fmaxf(x, 0.0f) + log1pf(expf(-fabsf(x)));
}

__device__ __forceinline__ __half2 u2h2(unsigned v) {
    return *reinterpret_cast<__half2*>(&v);
}

// ---------------------------------------------------------------------------
// Kernel 1: g[k][f] = softplus( sum_h softplus(d_k*w1+b1)*W2[h,f] + b2[f] )
// stored as half in the interleaved chunk layout. grid = Tn, block = Hn.
// ---------------------------------------------------------------------------
__global__ void build_table_kernel(const float* __restrict__ w1,
                                   const float* __restrict__ b1,
                                   const float* __restrict__ W2,
                                   const float* __restrict__ b2) {
    __shared__ float u[Hn];
    const int k = blockIdx.x;
    const int h = threadIdx.x;  // 0..127
    const float d = (float)k * (D_MAX / (float)(Tn - 1));
    u[h] = softplus_acc(fmaf(d, w1[h], b1[h]));
    __syncthreads();
    if (h < Fn) {
        float acc = b2[h];
#pragma unroll
        for (int hh = 0; hh < Hn; ++hh)
            acc = fmaf(u[hh], W2[hh * Fn + h], acc);
        const __half g = __float2half(softplus_acc(acc));
        __half* tabh = (__half*)g_table_raw;
        const int c = (h < 32) ? (h >> 2) : ((h - 32) >> 2);
        const int slot = (h < 32) ? (h & 3) : (4 + (h & 3));
        tabh[k * 64 + c * 8 + slot] = g;
    }
}

// ---------------------------------------------------------------------------
// Kernel 2: main reduction.
// grid = 128 CTAs (32 output rows each), block = 512 threads (16 warps).
// Thread (fq = tid&7, row = (tid>>3)&31, jh = tid>>8) owns features
// {4fq..4fq+3} u {32+4fq..32+4fq+3} of local row `row`, for j-half `jh`.
// Per (warp, j): table 4 wf, fv 2 wf, dsm 1 wf = 7 crossbar wavefronts.
// ---------------------------------------------------------------------------
__global__ void __launch_bounds__(512, 1)
mp_main_kernel(const float* __restrict__ r, const float* __restrict__ f,
               float* __restrict__ out) {
    extern __shared__ float sm[];
    char* tab = (char*)sm;                     // 1024*128B = 128 KB
    float* fsmA = sm + 32768;                  // [j][32] feats  0..31: 32 KB
    float* fsmB = fsmA + 8192;                 // [j][32] feats 32..63: 32 KB
    unsigned* dsm = (unsigned*)(fsmB + 8192);  // [j][32] byte offs:    32 KB

    const int tid = threadIdx.x;
    const int cta = blockIdx.x;             // 0..127
    const int b = cta >> 3;                 // 8 CTAs per batch element
    const int i0 = (cta & 7) * 32;          // first local row of this tile

    // 1) stage r[b] (256x3 floats) into the fsmA area temporarily
    for (int e = tid; e < Nn * 3; e += 512)
        fsmA[e] = r[b * Nn * 3 + e];
    __syncthreads();

    // 2) precompute nearest-entry byte offsets, dsm[j*32 + row]
    const float scale = (float)(Tn - 1) / D_MAX;
    for (int e = tid; e < 32 * Nn; e += 512) {
        const int j = e >> 5;
        const int row = e & 31;
        const int ig = i0 + row;
        const float dx = fsmA[ig * 3 + 0] - fsmA[j * 3 + 0];
        const float dy = fsmA[ig * 3 + 1] - fsmA[j * 3 + 1];
        const float dz = fsmA[ig * 3 + 2] - fsmA[j * 3 + 2];
        const float s = fmaf(dx, dx, fmaf(dy, dy, dz * dz));
        float d;
        asm("sqrt.approx.f32 %0, %1;" : "=f"(d) : "f"(s));  // sqrt.approx(0)=0
        int k = __float2int_rn(d * scale);
        k = min(k, Tn - 1);
        dsm[e] = (unsigned)k << 7;  // k * TROW
    }
    __syncthreads();

    // 3) stage f[b] into split half-tiles and copy the table
    for (int e = tid; e < (Nn * Fn) / 4; e += 512) {
        const int q = e & 15;   // feature group of 4
        const int j = e >> 4;
        const float4 v = ((const float4*)(f + b * Nn * Fn))[e];
        if (q < 8)
            *(float4*)(fsmA + j * 32 + q * 4) = v;
        else
            *(float4*)(fsmB + j * 32 + (q - 8) * 4) = v;
    }
    for (int e = tid; e < (Tn * TROW) / 16; e += 512)
        ((uint4*)tab)[e] = g_table_raw[e];
    __syncthreads();

    // 4) main loop over this thread's j-half
    const int fq = tid & 7;
    const int row = (tid >> 3) & 31;
    const int jh = tid >> 8;
    const char* tabp = tab + fq * 16;
    const float* fA = fsmA + fq * 4;
    const float* fB = fsmB + fq * 4;
    const unsigned* dp = dsm + row;
    const int jbase = jh << 7;

    float4 accA = make_float4(0.f, 0.f, 0.f, 0.f);
    float4 accB = make_float4(0.f, 0.f, 0.f, 0.f);

#pragma unroll 4
    for (int jj = 0; jj < 128; ++jj) {
        const int j = jbase + jj;
        const unsigned off = dp[j * 32];
        const uint4 v = *(const uint4*)(tabp + off);
        const float4 fa = *(const float4*)(fA + j * 32);
        const float4 fb = *(const float4*)(fB + j * 32);

        const float2 g01 = __half22float2(u2h2(v.x));
        const float2 g23 = __half22float2(u2h2(v.y));
        const float2 G01 = __half22float2(u2h2(v.z));
        const float2 G23 = __half22float2(u2h2(v.w));

        accA.x = fmaf(g01.x, fa.x, accA.x);
        accA.y = fmaf(g01.y, fa.y, accA.y);
        accA.z = fmaf(g23.x, fa.z, accA.z);
        accA.w = fmaf(g23.y, fa.w, accA.w);
        accB.x = fmaf(G01.x, fb.x, accB.x);
        accB.y = fmaf(G01.y, fb.y, accB.y);
        accB.z = fmaf(G23.x, fb.z, accB.z);
        accB.w = fmaf(G23.y, fb.w, accB.w);
    }

    // 5) cross-j-half reduction (scratch reuses dsm), softplus, store
    __syncthreads();
    float* red = (float*)dsm;
    if (jh) {
        float4* p = (float4*)(red + (tid & 255) * 8);
        p[0] = accA;
        p[1] = accB;
    }
    __syncthreads();
    if (!jh) {
        const float4* p = (const float4*)(red + tid * 8);
        const float4 pA = p[0];
        const float4 pB = p[1];
        const int rowg = cta * 32 + row;
        float4 oA, oB;
        oA.x = softplus_acc(accA.x + pA.x);
        oA.y = softplus_acc(accA.y + pA.y);
        oA.z = softplus_acc(accA.z + pA.z);
        oA.w = softplus_acc(accA.w + pA.w);
        oB.x = softplus_acc(accB.x + pB.x);
        oB.y = softplus_acc(accB.y + pB.y);
        oB.z = softplus_acc(accB.z + pB.z);
        oB.w = softplus_acc(accB.w + pB.w);
        *(float4*)(out + rowg * Fn + fq * 4) = oA;
        *(float4*)(out + rowg * Fn + 32 + fq * 4) = oB;
    }
}

// ---------------------------------------------------------------------------
extern "C" void kernel_launch(void* const* d_in, const int* in_sizes, int n_in,
                              void* d_out, int out_size) {
    const float* r_batch = (const float*)d_in[0];  // [16,256,3]
    const float* f_batch = (const float*)d_in[1];  // [16,256,64]
    const float* w1 = (const float*)d_in[2];       // [128]
    const float* b1 = (const float*)d_in[3];       // [128]
    const float* W2 = (const float*)d_in[4];       // [128,64]
    const float* b2 = (const float*)d_in[5];       // [64]
    float* out = (float*)d_out;                    // [16,256,64]

    build_table_kernel<<<Tn, Hn>>>(w1, b1, W2, b2);

    const int smem_bytes = 128 * 1024 + 3 * 32 * 1024;  // 224 KB
    static bool attr_set = false;
    if (!attr_set) {
        cudaFuncSetAttribute(mp_main_kernel,
                             cudaFuncAttributeMaxDynamicSharedMemorySize,
                             smem_bytes);
        attr_set = true;
    }
    mp_main_kernel<<<(Bn * Nn) / 32, 512, smem_bytes>>>(r_batch, f_batch, out);
}

// round 6
// speedup vs baseline: 1.5417x; 1.3667x over previous
#include <cuda_runtime.h>
#include <cuda_fp16.h>
#include <math.h>

// Problem constants
#define Bn 16
#define Nn 256
#define Fn 64
#define Hn 128

// Table constants (nearest-neighbor lookup)
#define Tn 1024
#define D_MAX 1.7320509f
#define TROW 128  // bytes per table row: 64 features x half

// Table row layout (interleaved for conflict-free LDS.128):
//   chunk c (16 bytes), c = 0..7:
//     halves [0..3] = g[k][4c .. 4c+3]
//     halves [4..7] = g[k][32+4c .. 32+4c+3]
__device__ uint4 g_table_raw[(Tn * TROW) / 16];

__device__ __forceinline__ float softplus_acc(float x) {
    // matches jax.nn.softplus = logaddexp(x, 0), stable for all x
    return fmaxf(x, 0.0f) + log1pf(expf(-fabsf(x)));
}

__device__ __forceinline__ __half2 u2h2(unsigned v) {
    return *reinterpret_cast<__half2*>(&v);
}

// ---------------------------------------------------------------------------
// Kernel 1: g[k][f] = softplus( sum_h softplus(d_k*w1+b1)*W2[h,f] + b2[f] )
// stored as half in the interleaved chunk layout. grid = Tn, block = Hn.
// ---------------------------------------------------------------------------
__global__ void build_table_kernel(const float* __restrict__ w1,
                                   const float* __restrict__ b1,
                                   const float* __restrict__ W2,
                                   const float* __restrict__ b2) {
    __shared__ float u[Hn];
    const int k = blockIdx.x;
    const int h = threadIdx.x;  // 0..127
    const float d = (float)k * (D_MAX / (float)(Tn - 1));
    u[h] = softplus_acc(fmaf(d, w1[h], b1[h]));
    __syncthreads();
    if (h < Fn) {
        float acc = b2[h];
#pragma unroll
        for (int hh = 0; hh < Hn; ++hh)
            acc = fmaf(u[hh], W2[hh * Fn + h], acc);
        const __half g = __float2half(softplus_acc(acc));
        __half* tabh = (__half*)g_table_raw;
        const int c = (h < 32) ? (h >> 2) : ((h - 32) >> 2);
        const int slot = (h < 32) ? (h & 3) : (4 + (h & 3));
        tabh[k * 64 + c * 8 + slot] = g;
    }
}

// ---------------------------------------------------------------------------
// Kernel 2: main reduction.
// grid = 128 CTAs (32 output rows each), block = 1024 threads (32 warps).
// Thread (fq = tid&7, row = (tid>>3)&31, jq = tid>>8) owns features
// {4fq..4fq+3} u {32+4fq..32+4fq+3} of local row `row`, j-quarter `jq`.
// Per (warp, j): table 4 wf, f-half 1 wf, dsm 1 wf = 6 crossbar wavefronts.
// ---------------------------------------------------------------------------
__global__ void __launch_bounds__(1024, 1)
mp_main_kernel(const float* __restrict__ r, const float* __restrict__ f,
               float* __restrict__ out) {
    extern __shared__ float sm[];
    char* tab = (char*)sm;                      // 1024*128B = 128 KB
    char* fh = (char*)sm + 131072;              // [j][64] half, interleaved: 32 KB
    unsigned* dsm = (unsigned*)(sm + 40960);    // [j][32] byte offs: 32 KB

    const int tid = threadIdx.x;
    const int cta = blockIdx.x;             // 0..127
    const int b = cta >> 3;                 // 8 CTAs per batch element
    const int i0 = (cta & 7) * 32;          // first local row of this tile

    // 1) stage r[b] (256x3 floats) into the fh area temporarily (as floats)
    float* rstage = (float*)fh;
    for (int e = tid; e < Nn * 3; e += 1024)
        rstage[e] = r[b * Nn * 3 + e];
    __syncthreads();

    // 2) precompute nearest-entry byte offsets, dsm[j*32 + row]
    const float scale = (float)(Tn - 1) / D_MAX;
    for (int e = tid; e < 32 * Nn; e += 1024) {
        const int j = e >> 5;
        const int row = e & 31;
        const int ig = i0 + row;
        const float dx = rstage[ig * 3 + 0] - rstage[j * 3 + 0];
        const float dy = rstage[ig * 3 + 1] - rstage[j * 3 + 1];
        const float dz = rstage[ig * 3 + 2] - rstage[j * 3 + 2];
        const float s = fmaf(dx, dx, fmaf(dy, dy, dz * dz));
        float d;
        asm("sqrt.approx.f32 %0, %1;" : "=f"(d) : "f"(s));  // sqrt.approx(0)=0
        int k = __float2int_rn(d * scale);
        k = min(k, Tn - 1);
        dsm[e] = (unsigned)k << 7;  // k * TROW
    }
    __syncthreads();

    // 3) stage f[b] as half in the table-matching interleaved layout, copy table
    for (int e = tid; e < Nn * (Fn / 4); e += 1024) {
        const int j = e >> 4;
        const int q = e & 15;
        const float4 v = ((const float4*)(f + b * Nn * Fn))[e];
        const __half2 h01 = __floats2half2_rn(v.x, v.y);
        const __half2 h23 = __floats2half2_rn(v.z, v.w);
        const int c = (q < 8) ? q : (q - 8);
        const int slot = (q < 8) ? 0 : 4;
        __half* dst = (__half*)fh + j * 64 + c * 8 + slot;
        *(__half2*)(dst) = h01;
        *(__half2*)(dst + 2) = h23;
    }
    for (int e = tid; e < (Tn * TROW) / 16; e += 1024)
        ((uint4*)tab)[e] = g_table_raw[e];
    __syncthreads();

    // 4) main loop over this thread's j-quarter (64 j)
    const int fq = tid & 7;
    const int row = (tid >> 3) & 31;
    const int jq = tid >> 8;
    const char* tabp = tab + fq * 16;
    const char* fhp = fh + fq * 16;
    const unsigned* dp = dsm + row;
    const int jbase = jq << 6;

    float4 accA = make_float4(0.f, 0.f, 0.f, 0.f);
    float4 accB = make_float4(0.f, 0.f, 0.f, 0.f);

#pragma unroll 8
    for (int jj = 0; jj < 64; ++jj) {
        const int j = jbase + jj;
        const unsigned off = dp[j * 32];
        const uint4 v = *(const uint4*)(tabp + off);
        const uint4 fv = *(const uint4*)(fhp + j * 128);

        const __half2 p0 = __hmul2(u2h2(v.x), u2h2(fv.x));
        const __half2 p1 = __hmul2(u2h2(v.y), u2h2(fv.y));
        const __half2 p2 = __hmul2(u2h2(v.z), u2h2(fv.z));
        const __half2 p3 = __hmul2(u2h2(v.w), u2h2(fv.w));
        const float2 q0 = __half22float2(p0);
        const float2 q1 = __half22float2(p1);
        const float2 q2 = __half22float2(p2);
        const float2 q3 = __half22float2(p3);

        accA.x += q0.x; accA.y += q0.y;
        accA.z += q1.x; accA.w += q1.y;
        accB.x += q2.x; accB.y += q2.y;
        accB.z += q3.x; accB.w += q3.y;
    }

    // 5) cross-quarter reduction (scratch reuses dsm), softplus, store
    __syncthreads();
    float* red = (float*)dsm;
    if (jq) {
        float4* p = (float4*)(red + ((jq - 1) * 256 + (tid & 255)) * 8);
        p[0] = accA;
        p[1] = accB;
    }
    __syncthreads();
    if (!jq) {
#pragma unroll
        for (int s = 0; s < 3; ++s) {
            const float4* p = (const float4*)(red + (s * 256 + tid) * 8);
            const float4 pA = p[0];
            const float4 pB = p[1];
            accA.x += pA.x; accA.y += pA.y; accA.z += pA.z; accA.w += pA.w;
            accB.x += pB.x; accB.y += pB.y; accB.z += pB.z; accB.w += pB.w;
        }
        const int rowg = cta * 32 + row;
        float4 oA, oB;
        oA.x = softplus_acc(accA.x); oA.y = softplus_acc(accA.y);
        oA.z = softplus_acc(accA.z); oA.w = softplus_acc(accA.w);
        oB.x = softplus_acc(accB.x); oB.y = softplus_acc(accB.y);
        oB.z = softplus_acc(accB.z); oB.w = softplus_acc(accB.w);
        *(float4*)(out + rowg * Fn + fq * 4) = oA;
        *(float4*)(out + rowg * Fn + 32 + fq * 4) = oB;
    }
}

// ---------------------------------------------------------------------------
extern "C" void kernel_launch(void* const* d_in, const int* in_sizes, int n_in,
                              void* d_out, int out_size) {
    const float* r_batch = (const float*)d_in[0];  // [16,256,3]
    const float* f_batch = (const float*)d_in[1];  // [16,256,64]
    const float* w1 = (const float*)d_in[2];       // [128]
    const float* b1 = (const float*)d_in[3];       // [128]
    const float* W2 = (const float*)d_in[4];       // [128,64]
    const float* b2 = (const float*)d_in[5];       // [64]
    float* out = (float*)d_out;                    // [16,256,64]

    build_table_kernel<<<Tn, Hn>>>(w1, b1, W2, b2);

    const int smem_bytes = 128 * 1024 + 32 * 1024 + 32 * 1024;  // 192 KB
    static bool attr_set = false;
    if (!attr_set) {
        cudaFuncSetAttribute(mp_main_kernel,
                             cudaFuncAttributeMaxDynamicSharedMemorySize,
                             smem_bytes);
        attr_set = true;
    }
    mp_main_kernel<<<(Bn * Nn) / 32, 1024, smem_bytes>>>(r_batch, f_batch, out);
}